// round 3
// baseline (speedup 1.0000x reference)
#include <cuda_runtime.h>
#include <math.h>

// Problem constants
#define NB   2
#define T    2048
#define DM   1024
#define H    8
#define E    4
#define L    32
#define DK   64
#define DV   64
#define NT   (NB * T)        // 4096 tokens
#define CQKV 1536            // Q|K|V output columns
#define TBUF (T + L - 1)     // 2079 rolling-state buffer length per (n,e)

// ---------------------------------------------------------------------------
// Scratch (static __device__ globals — no allocations allowed)
// ---------------------------------------------------------------------------
__device__ float g_wQKV[(size_t)CQKV * DM];           // fused Q|K|V weights
__device__ float g_QKV [(size_t)NT * CQKV];           // per-token Q|K|V projections
__device__ float g_A   [(size_t)NB * E * T];          // decay A[n,e,t]
__device__ float g_gK  [(size_t)NB * E * T * DK];     // gated K
__device__ float g_gV  [(size_t)NB * E * T * DV];     // gated V
__device__ float g_bK  [(size_t)NB * E * TBUF * DK];  // buf[p] = rec_K[p+1]
__device__ float g_bV  [(size_t)NB * E * TBUF * DV];
__device__ float g_Y   [(size_t)NT * (H * DV)];       // attention output

// ---------------------------------------------------------------------------
// 0) Concat w_Q | w_K | w_V into one (1536 x 1024) weight
// ---------------------------------------------------------------------------
__global__ void concat_w(const float* __restrict__ wq,
                         const float* __restrict__ wk,
                         const float* __restrict__ wv)
{
    const int sz = 512 * DM;
    int i = blockIdx.x * blockDim.x + threadIdx.x;
    if (i < sz) {
        g_wQKV[i]          = wq[i];
        g_wQKV[sz + i]     = wk[i];
        g_wQKV[2 * sz + i] = wv[i];
    }
}

// ---------------------------------------------------------------------------
// 1) fp32 tiled GEMM: C[M,N] = A[M,K] * B, 128x128 tile, BK=8, 256 threads,
//    8x8 per-thread microtile.
//    BN_LAYOUT==0: B is (N,K) row-major (weights: K contiguous)  ("NT")
//    BN_LAYOUT==1: B is (K,N) row-major (w_O: N contiguous)      ("NN")
// ---------------------------------------------------------------------------
template <int BN_LAYOUT>
__global__ __launch_bounds__(256)
void gemm128(const float* __restrict__ A, const float* __restrict__ B,
             float* __restrict__ C, int M, int N, int K)
{
    __shared__ float As[8 * 128];
    __shared__ float Bs[8 * 128];

    const int tid = threadIdx.x;
    const int m0 = blockIdx.x * 128;
    const int n0 = blockIdx.y * 128;
    const int tx = tid & 15;
    const int ty = tid >> 4;

    float acc[8][8];
#pragma unroll
    for (int i = 0; i < 8; ++i)
#pragma unroll
        for (int j = 0; j < 8; ++j) acc[i][j] = 0.f;

    const int ar  = tid >> 1;          // row within 128-row tile
    const int akq = (tid & 1) * 4;     // k quad
    const int bkr = tid >> 5;          // k row (NN layout)
    const int bnq = (tid & 31) * 4;    // n quad (NN layout)

    for (int k0 = 0; k0 < K; k0 += 8) {
        // Load A tile (transpose into As[k][m])
        {
            float4 v = *(const float4*)(A + (size_t)(m0 + ar) * K + k0 + akq);
            As[(akq + 0) * 128 + ar] = v.x;
            As[(akq + 1) * 128 + ar] = v.y;
            As[(akq + 2) * 128 + ar] = v.z;
            As[(akq + 3) * 128 + ar] = v.w;
        }
        // Load B tile into Bs[k][n]
        if (BN_LAYOUT == 0) {
            float4 v = *(const float4*)(B + (size_t)(n0 + ar) * K + k0 + akq);
            Bs[(akq + 0) * 128 + ar] = v.x;
            Bs[(akq + 1) * 128 + ar] = v.y;
            Bs[(akq + 2) * 128 + ar] = v.z;
            Bs[(akq + 3) * 128 + ar] = v.w;
        } else {
            float4 v = *(const float4*)(B + (size_t)(k0 + bkr) * N + n0 + bnq);
            *(float4*)(Bs + bkr * 128 + bnq) = v;
        }
        __syncthreads();

#pragma unroll
        for (int k = 0; k < 8; ++k) {
            float4 a0 = *(const float4*)(As + k * 128 + ty * 4);
            float4 a1 = *(const float4*)(As + k * 128 + 64 + ty * 4);
            float4 b0 = *(const float4*)(Bs + k * 128 + tx * 4);
            float4 b1 = *(const float4*)(Bs + k * 128 + 64 + tx * 4);
            float a[8] = {a0.x, a0.y, a0.z, a0.w, a1.x, a1.y, a1.z, a1.w};
            float b[8] = {b0.x, b0.y, b0.z, b0.w, b1.x, b1.y, b1.z, b1.w};
#pragma unroll
            for (int i = 0; i < 8; ++i)
#pragma unroll
                for (int j = 0; j < 8; ++j)
                    acc[i][j] = fmaf(a[i], b[j], acc[i][j]);
        }
        __syncthreads();
    }

#pragma unroll
    for (int i = 0; i < 8; ++i) {
        int m = m0 + ((i < 4) ? (ty * 4 + i) : (64 + ty * 4 + i - 4));
        float* cp = C + (size_t)m * N + n0;
        float4 v0 = make_float4(acc[i][0], acc[i][1], acc[i][2], acc[i][3]);
        float4 v1 = make_float4(acc[i][4], acc[i][5], acc[i][6], acc[i][7]);
        *(float4*)(cp + tx * 4)      = v0;
        *(float4*)(cp + 64 + tx * 4) = v1;
    }
}

// ---------------------------------------------------------------------------
// 2) Gating: per token, compute G (sigmoid of GEMV), A[e] = 1 - sum_h G[h,e],
//    gated K/V[e,d] = sum_h G[h,e] * K/V[h,d]
// ---------------------------------------------------------------------------
__global__ __launch_bounds__(256)
void gating_kernel(const float* __restrict__ X,
                   const float* __restrict__ wG,
                   const float* __restrict__ bGb)
{
    __shared__ float Gs[32];

    const int token = blockIdx.x;
    const int n = token >> 11;   // token / T
    const int t = token & 2047;
    const int tid = threadIdx.x;

    // Stage 0: G logits (32 outputs, 8 threads each over K=1024)
    {
        const int oi = tid >> 3;     // output 0..31 (he = h*4+e)
        const int li = tid & 7;
        const float* xr = X + (size_t)token * DM;
        const float* wr = wG + (size_t)oi * DM;
        float acc = 0.f;
        for (int j = li; j < DM; j += 8) acc += xr[j] * wr[j];
        for (int off = 4; off; off >>= 1)
            acc += __shfl_down_sync(0xffffffffu, acc, off, 8);
        if (li == 0)
            Gs[oi] = 1.f / (1.f + __expf(-(acc + bGb[oi])));
    }
    __syncthreads();

    // Stage 1: A
    if (tid < E) {
        float s = 0.f;
#pragma unroll
        for (int h = 0; h < H; ++h) s += Gs[h * E + tid];
        g_A[(size_t)(n * E + tid) * T + t] = 1.f - s;
    }

    // Stage 2: gated K / V
    const int e = tid >> 6;          // 0..3
    const int d = tid & 63;
    const float* Kr = g_QKV + (size_t)token * CQKV + 512;
    const float* Vr = g_QKV + (size_t)token * CQKV + 1024;
    float ak = 0.f, av = 0.f;
#pragma unroll
    for (int h = 0; h < H; ++h) {
        float g = Gs[h * E + e];
        ak = fmaf(g, Kr[h * 64 + d], ak);
        av = fmaf(g, Vr[h * 64 + d], av);
    }
    size_t o = ((size_t)(n * E + e) * T + t) * 64 + d;
    g_gK[o] = ak;
    g_gV[o] = av;
}

// ---------------------------------------------------------------------------
// 3) Scan: 2(n)*4(e)*32(slot)*64(d)*2(K/V) = 32768 independent 64-step chains.
//    buf[p] = rec[p+1]: p<31 -> init slot p+1; p>=31 -> state after step p-31.
// ---------------------------------------------------------------------------
__global__ __launch_bounds__(256)
void scan_kernel(const float* __restrict__ initK,
                 const float* __restrict__ initV)
{
    const int id = blockIdx.x * 256 + threadIdx.x;   // 0..32767
    const int kv = id >> 14;
    const int c  = id & 16383;
    const int d  = c & 63;
    const int s  = (c >> 6) & 31;
    const int e  = (c >> 11) & 3;
    const int n  = c >> 13;

    const float* init = kv ? initV : initK;
    const float* g    = kv ? g_gV  : g_gK;
    float*       buf  = kv ? g_bV  : g_bK;

    const size_t ne = (size_t)(n * E + e);

    // init fill of buf[0..30] (chains with s<31 each cover one entry)
    if (s < 31)
        buf[(ne * TBUF + s) * 64 + d] = init[(e * L + s + 1) * 64 + d];

    float S = init[(e * L + s) * 64 + d];
    const float* Ap = g_A + ne * T + s;
    const float* gp = g + (ne * T + s) * 64 + d;
    float* bp = buf + (ne * TBUF + 31 + s) * 64 + d;

#pragma unroll 4
    for (int m = 0; m < T / L; ++m) {
        float a = Ap[(size_t)32 * m];
        S = fmaf(a, S, gp[(size_t)32 * m * 64]);
        bp[(size_t)32 * m * 64] = S;
    }
}

// ---------------------------------------------------------------------------
// 4) Attention: one block per token. Keys/values = current state after step t:
//    128 vectors (e x slot) of dim 64 read from buf window [t, t+32).
//    Warp w handles head w: 128 scores -> softmax -> 64-dim output.
// ---------------------------------------------------------------------------
__global__ __launch_bounds__(256)
void attn_kernel()
{
    __shared__ float kvs[128 * 65];   // K then V (staged), padded rows
    __shared__ float qsh[512];
    __shared__ float sc[8 * 128];

    const int token = blockIdx.x;
    const int n = token >> 11;
    const int t = token & 2047;
    const int tid = threadIdx.x;

    // load Q (cols 0..511 of QKV)
    for (int i = tid; i < 512; i += 256)
        qsh[i] = g_QKV[(size_t)token * CQKV + i];

    // load K window
    const float* bK = g_bK + (size_t)n * E * TBUF * 64;
    for (int idx = tid; idx < 128 * 64; idx += 256) {
        int row = idx >> 6, d = idx & 63;
        int e = row >> 5, j = row & 31;
        kvs[row * 65 + d] = bK[((size_t)e * TBUF + t + j) * 64 + d];
    }
    __syncthreads();

    const int w = tid >> 5;       // head
    const int lane = tid & 31;

    float sv[4];
    float mx = -1e30f;
#pragma unroll
    for (int kk = 0; kk < 4; ++kk) {
        int j = lane + kk * 32;
        const float* qp = qsh + w * 64;
        const float* kp = kvs + j * 65;
        float acc = 0.f;
#pragma unroll
        for (int d = 0; d < 64; ++d) acc = fmaf(qp[d], kp[d], acc);
        sv[kk] = acc * 0.125f;    // 1/sqrt(64)
        mx = fmaxf(mx, sv[kk]);
    }
    for (int off = 16; off; off >>= 1)
        mx = fmaxf(mx, __shfl_xor_sync(0xffffffffu, mx, off));
    float ssum = 0.f;
#pragma unroll
    for (int kk = 0; kk < 4; ++kk) {
        sv[kk] = __expf(sv[kk] - mx);
        ssum += sv[kk];
    }
    for (int off = 16; off; off >>= 1)
        ssum += __shfl_xor_sync(0xffffffffu, ssum, off);
    float inv = 1.f / ssum;
#pragma unroll
    for (int kk = 0; kk < 4; ++kk)
        sc[w * 128 + lane + kk * 32] = sv[kk] * inv;
    __syncthreads();

    // load V window (overwrite kvs)
    const float* bV = g_bV + (size_t)n * E * TBUF * 64;
    for (int idx = tid; idx < 128 * 64; idx += 256) {
        int row = idx >> 6, d = idx & 63;
        int e = row >> 5, j = row & 31;
        kvs[row * 65 + d] = bV[((size_t)e * TBUF + t + j) * 64 + d];
    }
    __syncthreads();

    float a0 = 0.f, a1 = 0.f;
    const float* pw = sc + w * 128;
#pragma unroll 4
    for (int j = 0; j < 128; ++j) {
        float p = pw[j];
        a0 = fmaf(p, kvs[j * 65 + lane], a0);
        a1 = fmaf(p, kvs[j * 65 + 32 + lane], a1);
    }
    g_Y[(size_t)token * 512 + w * 64 + lane]      = a0;
    g_Y[(size_t)token * 512 + w * 64 + 32 + lane] = a1;
}

// ---------------------------------------------------------------------------
// Launch
// ---------------------------------------------------------------------------
extern "C" void kernel_launch(void* const* d_in, const int* in_sizes, int n_in,
                              void* d_out, int out_size)
{
    (void)in_sizes; (void)n_in; (void)out_size;

    const float* X  = (const float*)d_in[0];
    const float* wG = (const float*)d_in[1];
    const float* bG = (const float*)d_in[2];
    const float* wK = (const float*)d_in[3];
    const float* wV = (const float*)d_in[4];
    const float* wQ = (const float*)d_in[5];
    const float* wO = (const float*)d_in[6];
    const float* iK = (const float*)d_in[7];
    const float* iV = (const float*)d_in[8];

    float *p_wQKV, *p_QKV, *p_Y;
    cudaGetSymbolAddress((void**)&p_wQKV, g_wQKV);
    cudaGetSymbolAddress((void**)&p_QKV,  g_QKV);
    cudaGetSymbolAddress((void**)&p_Y,    g_Y);

    concat_w<<<(512 * DM + 255) / 256, 256>>>(wQ, wK, wV);
    gemm128<0><<<dim3(NT / 128, CQKV / 128), 256>>>(X, p_wQKV, p_QKV, NT, CQKV, DM);
    gating_kernel<<<NT, 256>>>(X, wG, bG);
    scan_kernel<<<128, 256>>>(iK, iV);
    attn_kernel<<<NT, 256>>>();
    gemm128<1><<<dim3(NT / 128, DM / 128), 256>>>(p_Y, wO, (float*)d_out, NT, DM, H * DV);
}

// round 5
// speedup vs baseline: 1.3890x; 1.3890x over previous
#include <cuda_runtime.h>
#include <math.h>
#include <stdint.h>

// Problem constants
#define NB   2
#define T    2048
#define DM   1024
#define H    8
#define E    4
#define L    32
#define DK   64
#define DV   64
#define NT   (NB * T)        // 4096 tokens
#define CQKV 1536            // Q|K|V output columns
#define TBUF (T + L - 1)     // 2079 rolling-state buffer length per (n,e)

// ---------------------------------------------------------------------------
// Scratch (static __device__ globals — no allocations allowed)
// ---------------------------------------------------------------------------
__device__ float g_wQKV[(size_t)CQKV * DM];           // fused Q|K|V weights
__device__ float g_QKV [(size_t)NT * CQKV];           // per-token Q|K|V projections
__device__ float g_A   [(size_t)NB * E * T];          // decay A[n,e,t]
__device__ float g_gK  [(size_t)NB * E * T * DK];     // gated K
__device__ float g_gV  [(size_t)NB * E * T * DV];     // gated V
__device__ float g_bK  [(size_t)NB * E * TBUF * DK];  // buf[p] = rec_K[p+1]
__device__ float g_bV  [(size_t)NB * E * TBUF * DV];
__device__ float g_Y   [(size_t)NT * (H * DV)];       // attention output

__device__ __forceinline__ float tf32r(float x)
{
    asm("cvt.rna.tf32.f32 %0, %0;" : "+f"(x));
    return x;
}

// ---------------------------------------------------------------------------
// 0) Concat w_Q | w_K | w_V into one (1536 x 1024) weight
// ---------------------------------------------------------------------------
__global__ void concat_w(const float* __restrict__ wq,
                         const float* __restrict__ wk,
                         const float* __restrict__ wv)
{
    const int sz = 512 * DM;
    int i = blockIdx.x * blockDim.x + threadIdx.x;
    if (i < sz) {
        g_wQKV[i]          = wq[i];
        g_wQKV[sz + i]     = wk[i];
        g_wQKV[2 * sz + i] = wv[i];
    }
}

// ---------------------------------------------------------------------------
// 1) 3xTF32 tensor-core GEMM: C[M,N] = A[M,K] * B, ~fp32 accuracy.
//    Each operand split hi/lo; acc += hi*hi + lo*hi + hi*lo.
//    Block tile 128x128, BK=16, double-buffered cp.async, 256 threads.
//    8 warps in 2(m) x 4(n); warp tile 64x32 = 4x4 m16n8k8 mma tiles.
//    BLAYOUT==0: B is (N,K) row-major, K contiguous (weights)
//    BLAYOUT==1: B is (K,N) row-major, N contiguous (w_O)
// ---------------------------------------------------------------------------
template <int BLAYOUT>
__global__ __launch_bounds__(256)
void gemm_3xtf32(const float* __restrict__ A, const float* __restrict__ B,
                 float* __restrict__ C, int M, int N, int K)
{
    __shared__ float As[2][128 * 20];
    constexpr int BS_SZ = (BLAYOUT == 0) ? 128 * 20 : 16 * 136;
    __shared__ float Bs[2][BS_SZ];

    const int tid  = threadIdx.x;
    const int m0   = blockIdx.x * 128;
    const int n0   = blockIdx.y * 128;
    const int warp = tid >> 5;
    const int lane = tid & 31;
    const int wm   = (warp >> 2) * 64;   // 0 or 64
    const int wn   = (warp & 3) * 32;    // 0,32,64,96
    const int g    = lane >> 2;          // groupID 0..7
    const int t4   = lane & 3;           // threadID_in_group

    float acc[4][4][4] = {};

    auto loadA = [&](int s, int k0) {
#pragma unroll
        for (int c0 = 0; c0 < 2; ++c0) {
            int c   = tid + c0 * 256;
            int row = c >> 2;
            int q   = (c & 3) * 4;
            const float* src = A + (size_t)(m0 + row) * K + k0 + q;
            uint32_t dst = (uint32_t)__cvta_generic_to_shared(&As[s][row * 20 + q]);
            asm volatile("cp.async.cg.shared.global [%0], [%1], 16;\n"
                         :: "r"(dst), "l"(src));
        }
    };

    auto loadB = [&](int s, int k0) {
#pragma unroll
        for (int c0 = 0; c0 < 2; ++c0) {
            int c = tid + c0 * 256;
            if (BLAYOUT == 0) {
                int row = c >> 2;
                int q   = (c & 3) * 4;
                const float* src = B + (size_t)(n0 + row) * K + k0 + q;
                uint32_t dst = (uint32_t)__cvta_generic_to_shared(&Bs[s][row * 20 + q]);
                asm volatile("cp.async.cg.shared.global [%0], [%1], 16;\n"
                             :: "r"(dst), "l"(src));
            } else {
                int row = c >> 5;
                int q   = (c & 31) * 4;
                const float* src = B + (size_t)(k0 + row) * N + n0 + q;
                uint32_t dst = (uint32_t)__cvta_generic_to_shared(&Bs[s][row * 136 + q]);
                asm volatile("cp.async.cg.shared.global [%0], [%1], 16;\n"
                             :: "r"(dst), "l"(src));
            }
        }
    };

    loadA(0, 0);
    loadB(0, 0);
    asm volatile("cp.async.commit_group;\n");

    const int KB = K / 16;
    for (int kb = 0; kb < KB; ++kb) {
        const int cur = kb & 1;
        if (kb + 1 < KB) {
            loadA(cur ^ 1, (kb + 1) * 16);
            loadB(cur ^ 1, (kb + 1) * 16);
            asm volatile("cp.async.commit_group;\n");
            asm volatile("cp.async.wait_group 1;\n");
        } else {
            asm volatile("cp.async.wait_group 0;\n");
        }
        __syncthreads();

#pragma unroll
        for (int kk = 0; kk < 16; kk += 8) {
            uint32_t afh[4][4], afl[4][4];
#pragma unroll
            for (int mt = 0; mt < 4; ++mt) {
                int r0 = (wm + mt * 16 + g) * 20;
                int r1 = (wm + mt * 16 + g + 8) * 20;
                float f[4] = { As[cur][r0 + kk + t4],
                               As[cur][r1 + kk + t4],
                               As[cur][r0 + kk + t4 + 4],
                               As[cur][r1 + kk + t4 + 4] };
#pragma unroll
                for (int i = 0; i < 4; ++i) {
                    float hi = tf32r(f[i]);
                    afh[mt][i] = __float_as_uint(hi);
                    afl[mt][i] = __float_as_uint(f[i] - hi);
                }
            }
            uint32_t bfh[4][2], bfl[4][2];
#pragma unroll
            for (int nt = 0; nt < 4; ++nt) {
                float f[2];
                if (BLAYOUT == 0) {
                    int rb = (wn + nt * 8 + g) * 20;
                    f[0] = Bs[cur][rb + kk + t4];
                    f[1] = Bs[cur][rb + kk + t4 + 4];
                } else {
                    int col = wn + nt * 8 + g;
                    f[0] = Bs[cur][(kk + t4) * 136 + col];
                    f[1] = Bs[cur][(kk + t4 + 4) * 136 + col];
                }
#pragma unroll
                for (int i = 0; i < 2; ++i) {
                    float hi = tf32r(f[i]);
                    bfh[nt][i] = __float_as_uint(hi);
                    bfl[nt][i] = __float_as_uint(f[i] - hi);
                }
            }
#define MMA_TF32(AF, BF)                                                     \
    asm volatile(                                                            \
        "mma.sync.aligned.m16n8k8.row.col.f32.tf32.tf32.f32 "                \
        "{%0,%1,%2,%3}, {%4,%5,%6,%7}, {%8,%9}, {%0,%1,%2,%3};"              \
        : "+f"(acc[mt][nt][0]), "+f"(acc[mt][nt][1]),                        \
          "+f"(acc[mt][nt][2]), "+f"(acc[mt][nt][3])                         \
        : "r"(AF[mt][0]), "r"(AF[mt][1]), "r"(AF[mt][2]), "r"(AF[mt][3]),    \
          "r"(BF[nt][0]), "r"(BF[nt][1]))

#pragma unroll
            for (int mt = 0; mt < 4; ++mt)
#pragma unroll
                for (int nt = 0; nt < 4; ++nt) {
                    MMA_TF32(afl, bfh);   // lo*hi (smallest first)
                    MMA_TF32(afh, bfl);   // hi*lo
                    MMA_TF32(afh, bfh);   // hi*hi
                }
#undef MMA_TF32
        }
        __syncthreads();
    }

    // Epilogue
#pragma unroll
    for (int mt = 0; mt < 4; ++mt) {
        int r0 = m0 + wm + mt * 16 + g;
#pragma unroll
        for (int nt = 0; nt < 4; ++nt) {
            int cc = n0 + wn + nt * 8 + 2 * t4;
            *(float2*)&C[(size_t)r0 * N + cc] =
                make_float2(acc[mt][nt][0], acc[mt][nt][1]);
            *(float2*)&C[(size_t)(r0 + 8) * N + cc] =
                make_float2(acc[mt][nt][2], acc[mt][nt][3]);
        }
    }
}

// ---------------------------------------------------------------------------
// 2) Gating
// ---------------------------------------------------------------------------
__global__ __launch_bounds__(256)
void gating_kernel(const float* __restrict__ X,
                   const float* __restrict__ wG,
                   const float* __restrict__ bGb)
{
    __shared__ float Gs[32];

    const int token = blockIdx.x;
    const int n = token >> 11;
    const int t = token & 2047;
    const int tid = threadIdx.x;

    {
        const int oi = tid >> 3;
        const int li = tid & 7;
        const float* xr = X + (size_t)token * DM;
        const float* wr = wG + (size_t)oi * DM;
        float acc = 0.f;
        for (int j = li; j < DM; j += 8) acc += xr[j] * wr[j];
        for (int off = 4; off; off >>= 1)
            acc += __shfl_down_sync(0xffffffffu, acc, off, 8);
        if (li == 0)
            Gs[oi] = 1.f / (1.f + __expf(-(acc + bGb[oi])));
    }
    __syncthreads();

    if (tid < E) {
        float s = 0.f;
#pragma unroll
        for (int h = 0; h < H; ++h) s += Gs[h * E + tid];
        g_A[(size_t)(n * E + tid) * T + t] = 1.f - s;
    }

    const int e = tid >> 6;
    const int d = tid & 63;
    const float* Kr = g_QKV + (size_t)token * CQKV + 512;
    const float* Vr = g_QKV + (size_t)token * CQKV + 1024;
    float ak = 0.f, av = 0.f;
#pragma unroll
    for (int h = 0; h < H; ++h) {
        float gg = Gs[h * E + e];
        ak = fmaf(gg, Kr[h * 64 + d], ak);
        av = fmaf(gg, Vr[h * 64 + d], av);
    }
    size_t o = ((size_t)(n * E + e) * T + t) * 64 + d;
    g_gK[o] = ak;
    g_gV[o] = av;
}

// ---------------------------------------------------------------------------
// 3) Scan: one thread per (n,e,s,d) runs BOTH the K and V 64-step chains.
// ---------------------------------------------------------------------------
__global__ __launch_bounds__(256)
void scan_kernel(const float* __restrict__ Aarr,
                 const float* __restrict__ gK, const float* __restrict__ gV,
                 float* __restrict__ bK, float* __restrict__ bV,
                 const float* __restrict__ iK, const float* __restrict__ iV)
{
    const int id = blockIdx.x * 256 + threadIdx.x;   // 0..16383
    const int d  = id & 63;
    const int s  = (id >> 6) & 31;
    const int e  = (id >> 11) & 3;
    const int n  = id >> 13;

    const size_t ne = (size_t)(n * E + e);

    if (s < 31) {
        bK[(ne * TBUF + s) * 64 + d] = iK[(e * L + s + 1) * 64 + d];
        bV[(ne * TBUF + s) * 64 + d] = iV[(e * L + s + 1) * 64 + d];
    }

    float SK = iK[(e * L + s) * 64 + d];
    float SV = iV[(e * L + s) * 64 + d];
    const float* Ap = Aarr + ne * T + s;
    const size_t off  = (ne * T + s) * 64 + d;
    const size_t boff = (ne * TBUF + 31 + s) * 64 + d;

#pragma unroll 4
    for (int m = 0; m < T / L; ++m) {
        float a = Ap[(size_t)32 * m];
        SK = fmaf(a, SK, gK[off + (size_t)2048 * m]);
        SV = fmaf(a, SV, gV[off + (size_t)2048 * m]);
        bK[boff + (size_t)2048 * m] = SK;
        bV[boff + (size_t)2048 * m] = SV;
    }
}

// ---------------------------------------------------------------------------
// 4) Attention: one block per token; warp w = head w; 128 state vectors.
// ---------------------------------------------------------------------------
__global__ __launch_bounds__(256)
void attn_kernel()
{
    __shared__ float kvs[128 * 65];
    __shared__ float qsh[512];
    __shared__ float sc[8 * 128];

    const int token = blockIdx.x;
    const int n = token >> 11;
    const int t = token & 2047;
    const int tid = threadIdx.x;

    for (int i = tid; i < 512; i += 256)
        qsh[i] = g_QKV[(size_t)token * CQKV + i];

    const float* bK = g_bK + (size_t)n * E * TBUF * 64;
    for (int idx = tid; idx < 128 * 64; idx += 256) {
        int row = idx >> 6, d = idx & 63;
        int e = row >> 5, j = row & 31;
        kvs[row * 65 + d] = bK[((size_t)e * TBUF + t + j) * 64 + d];
    }
    __syncthreads();

    const int w = tid >> 5;
    const int lane = tid & 31;

    float sv[4];
    float mx = -1e30f;
#pragma unroll
    for (int kk = 0; kk < 4; ++kk) {
        int j = lane + kk * 32;
        const float* qp = qsh + w * 64;
        const float* kp = kvs + j * 65;
        float acc = 0.f;
#pragma unroll
        for (int d = 0; d < 64; ++d) acc = fmaf(qp[d], kp[d], acc);
        sv[kk] = acc * 0.125f;
        mx = fmaxf(mx, sv[kk]);
    }
    for (int off = 16; off; off >>= 1)
        mx = fmaxf(mx, __shfl_xor_sync(0xffffffffu, mx, off));
    float ssum = 0.f;
#pragma unroll
    for (int kk = 0; kk < 4; ++kk) {
        sv[kk] = __expf(sv[kk] - mx);
        ssum += sv[kk];
    }
    for (int off = 16; off; off >>= 1)
        ssum += __shfl_xor_sync(0xffffffffu, ssum, off);
    float inv = 1.f / ssum;
#pragma unroll
    for (int kk = 0; kk < 4; ++kk)
        sc[w * 128 + lane + kk * 32] = sv[kk] * inv;
    __syncthreads();

    const float* bV = g_bV + (size_t)n * E * TBUF * 64;
    for (int idx = tid; idx < 128 * 64; idx += 256) {
        int row = idx >> 6, d = idx & 63;
        int e = row >> 5, j = row & 31;
        kvs[row * 65 + d] = bV[((size_t)e * TBUF + t + j) * 64 + d];
    }
    __syncthreads();

    float a0 = 0.f, a1 = 0.f;
    const float* pw = sc + w * 128;
#pragma unroll 4
    for (int j = 0; j < 128; ++j) {
        float p = pw[j];
        a0 = fmaf(p, kvs[j * 65 + lane], a0);
        a1 = fmaf(p, kvs[j * 65 + 32 + lane], a1);
    }
    g_Y[(size_t)token * 512 + w * 64 + lane]      = a0;
    g_Y[(size_t)token * 512 + w * 64 + 32 + lane] = a1;
}

// ---------------------------------------------------------------------------
// Launch
// ---------------------------------------------------------------------------
extern "C" void kernel_launch(void* const* d_in, const int* in_sizes, int n_in,
                              void* d_out, int out_size)
{
    (void)in_sizes; (void)n_in; (void)out_size;

    const float* X  = (const float*)d_in[0];
    const float* wG = (const float*)d_in[1];
    const float* bG = (const float*)d_in[2];
    const float* wK = (const float*)d_in[3];
    const float* wV = (const float*)d_in[4];
    const float* wQ = (const float*)d_in[5];
    const float* wO = (const float*)d_in[6];
    const float* iK = (const float*)d_in[7];
    const float* iV = (const float*)d_in[8];

    float *p_wQKV, *p_QKV, *p_Y, *p_A, *p_gK, *p_gV, *p_bK, *p_bV;
    cudaGetSymbolAddress((void**)&p_wQKV, g_wQKV);
    cudaGetSymbolAddress((void**)&p_QKV,  g_QKV);
    cudaGetSymbolAddress((void**)&p_Y,    g_Y);
    cudaGetSymbolAddress((void**)&p_A,    g_A);
    cudaGetSymbolAddress((void**)&p_gK,   g_gK);
    cudaGetSymbolAddress((void**)&p_gV,   g_gV);
    cudaGetSymbolAddress((void**)&p_bK,   g_bK);
    cudaGetSymbolAddress((void**)&p_bV,   g_bV);

    concat_w<<<(512 * DM + 255) / 256, 256>>>(wQ, wK, wV);
    gemm_3xtf32<0><<<dim3(NT / 128, CQKV / 128), 256>>>(X, p_wQKV, p_QKV, NT, CQKV, DM);
    gating_kernel<<<NT, 256>>>(X, wG, bG);
    scan_kernel<<<64, 256>>>(p_A, p_gK, p_gV, p_bK, p_bV, iK, iV);
    attn_kernel<<<NT, 256>>>();
    gemm_3xtf32<1><<<dim3(NT / 128, DM / 128), 256>>>(p_Y, wO, (float*)d_out, NT, DM, H * DV);
}

// round 6
// speedup vs baseline: 1.4019x; 1.0093x over previous
#include <cuda_runtime.h>
#include <cuda_bf16.h>
#include <math.h>
#include <stdint.h>

// Problem constants
#define NB   2
#define T    2048
#define DM   1024
#define H    8
#define E    4
#define L    32
#define DK   64
#define DV   64
#define NT   (NB * T)        // 4096 tokens
#define CQKV 1536            // Q|K|V output columns
#define TBUF (T + L - 1)     // 2079 rolling-state buffer length per (n,e)

// ---------------------------------------------------------------------------
// Scratch (static __device__ globals — no allocations allowed)
// ---------------------------------------------------------------------------
__device__ float g_wQKV[(size_t)CQKV * DM];           // fused Q|K|V weights
__device__ float g_QKV [(size_t)NT * CQKV];           // per-token Q|K|V projections
__device__ float g_A   [(size_t)NB * E * T];          // decay A[n,e,t]
__device__ float g_gK  [(size_t)NB * E * T * DK];     // gated K
__device__ float g_gV  [(size_t)NB * E * T * DV];     // gated V
__device__ float g_bK  [(size_t)NB * E * TBUF * DK];  // buf[p] = rec_K[p+1]
__device__ float g_bV  [(size_t)NB * E * TBUF * DV];
__device__ float g_Y   [(size_t)NT * (H * DV)];       // attention output

// ---------------------------------------------------------------------------
// 0) Concat w_Q | w_K | w_V into one (1536 x 1024) weight
// ---------------------------------------------------------------------------
__global__ void concat_w(const float* __restrict__ wq,
                         const float* __restrict__ wk,
                         const float* __restrict__ wv)
{
    const int sz = 512 * DM;
    int i = blockIdx.x * blockDim.x + threadIdx.x;
    if (i < sz) {
        g_wQKV[i]          = wq[i];
        g_wQKV[sz + i]     = wk[i];
        g_wQKV[2 * sz + i] = wv[i];
    }
}

// Split two fp32 values into packed bf16 hi and lo pairs (lo = x - hi).
__device__ __forceinline__ void split2(float x, float y,
                                       uint32_t& hi, uint32_t& lo)
{
    __nv_bfloat16 hx = __float2bfloat16_rn(x);
    __nv_bfloat16 hy = __float2bfloat16_rn(y);
    float lx = x - __bfloat162float(hx);
    float ly = y - __bfloat162float(hy);
    __nv_bfloat162 hp; hp.x = hx; hp.y = hy;
    __nv_bfloat162 lp = __floats2bfloat162_rn(lx, ly);
    hi = *reinterpret_cast<uint32_t*>(&hp);
    lo = *reinterpret_cast<uint32_t*>(&lp);
}

// ---------------------------------------------------------------------------
// 1) 3xBF16 tensor-core GEMM: C[M,N] = A[M,K] * B, ~fp32 accuracy.
//    Each operand split hi/lo (bf16); acc += hi*hi + lo*hi + hi*lo (fp32 acc).
//    Block tile 128x128, BK=16, double-buffered cp.async, 256 threads.
//    8 warps in 2(m) x 4(n); warp tile 64x32 = 4x4 m16n8k16 mma tiles.
//    BLAYOUT==0: B is (N,K) row-major, K contiguous (weights)
//    BLAYOUT==1: B is (K,N) row-major, N contiguous (w_O)
// ---------------------------------------------------------------------------
template <int BLAYOUT>
__global__ __launch_bounds__(256)
void gemm_3xbf16(const float* __restrict__ A, const float* __restrict__ B,
                 float* __restrict__ C, int M, int N, int K)
{
    __shared__ float As[2][128 * 20];
    constexpr int BS_SZ = (BLAYOUT == 0) ? 128 * 20 : 16 * 136;
    __shared__ float Bs[2][BS_SZ];

    const int tid  = threadIdx.x;
    const int m0   = blockIdx.x * 128;
    const int n0   = blockIdx.y * 128;
    const int warp = tid >> 5;
    const int lane = tid & 31;
    const int wm   = (warp >> 2) * 64;   // 0 or 64
    const int wn   = (warp & 3) * 32;    // 0,32,64,96
    const int g    = lane >> 2;          // groupID 0..7
    const int t4   = lane & 3;           // threadID_in_group

    float acc[4][4][4] = {};

    auto loadA = [&](int s, int k0) {
#pragma unroll
        for (int c0 = 0; c0 < 2; ++c0) {
            int c   = tid + c0 * 256;
            int row = c >> 2;
            int q   = (c & 3) * 4;
            const float* src = A + (size_t)(m0 + row) * K + k0 + q;
            uint32_t dst = (uint32_t)__cvta_generic_to_shared(&As[s][row * 20 + q]);
            asm volatile("cp.async.cg.shared.global [%0], [%1], 16;\n"
                         :: "r"(dst), "l"(src));
        }
    };

    auto loadB = [&](int s, int k0) {
#pragma unroll
        for (int c0 = 0; c0 < 2; ++c0) {
            int c = tid + c0 * 256;
            if (BLAYOUT == 0) {
                int row = c >> 2;
                int q   = (c & 3) * 4;
                const float* src = B + (size_t)(n0 + row) * K + k0 + q;
                uint32_t dst = (uint32_t)__cvta_generic_to_shared(&Bs[s][row * 20 + q]);
                asm volatile("cp.async.cg.shared.global [%0], [%1], 16;\n"
                             :: "r"(dst), "l"(src));
            } else {
                int row = c >> 5;
                int q   = (c & 31) * 4;
                const float* src = B + (size_t)(k0 + row) * N + n0 + q;
                uint32_t dst = (uint32_t)__cvta_generic_to_shared(&Bs[s][row * 136 + q]);
                asm volatile("cp.async.cg.shared.global [%0], [%1], 16;\n"
                             :: "r"(dst), "l"(src));
            }
        }
    };

    loadA(0, 0);
    loadB(0, 0);
    asm volatile("cp.async.commit_group;\n");

    const int KB = K / 16;
    for (int kb = 0; kb < KB; ++kb) {
        const int cur = kb & 1;
        if (kb + 1 < KB) {
            loadA(cur ^ 1, (kb + 1) * 16);
            loadB(cur ^ 1, (kb + 1) * 16);
            asm volatile("cp.async.commit_group;\n");
            asm volatile("cp.async.wait_group 1;\n");
        } else {
            asm volatile("cp.async.wait_group 0;\n");
        }
        __syncthreads();

        // A fragments for m16n8k16: rows {g, g+8}, k cols {2t4,2t4+1,2t4+8,2t4+9}
        uint32_t ah[4][4], al[4][4];
#pragma unroll
        for (int mt = 0; mt < 4; ++mt) {
            int r0 = (wm + mt * 16 + g) * 20;
            int r1 = (wm + mt * 16 + g + 8) * 20;
            split2(As[cur][r0 + 2 * t4],     As[cur][r0 + 2 * t4 + 1], ah[mt][0], al[mt][0]);
            split2(As[cur][r1 + 2 * t4],     As[cur][r1 + 2 * t4 + 1], ah[mt][1], al[mt][1]);
            split2(As[cur][r0 + 2 * t4 + 8], As[cur][r0 + 2 * t4 + 9], ah[mt][2], al[mt][2]);
            split2(As[cur][r1 + 2 * t4 + 8], As[cur][r1 + 2 * t4 + 9], ah[mt][3], al[mt][3]);
        }
        // B fragments: k rows {2t4,2t4+1,2t4+8,2t4+9}, col n = wn+nt*8+g
        uint32_t bh[4][2], bl[4][2];
#pragma unroll
        for (int nt = 0; nt < 4; ++nt) {
            float f0, f1, f2, f3;
            if (BLAYOUT == 0) {
                int rb = (wn + nt * 8 + g) * 20;
                f0 = Bs[cur][rb + 2 * t4];
                f1 = Bs[cur][rb + 2 * t4 + 1];
                f2 = Bs[cur][rb + 2 * t4 + 8];
                f3 = Bs[cur][rb + 2 * t4 + 9];
            } else {
                int col = wn + nt * 8 + g;
                f0 = Bs[cur][(2 * t4) * 136 + col];
                f1 = Bs[cur][(2 * t4 + 1) * 136 + col];
                f2 = Bs[cur][(2 * t4 + 8) * 136 + col];
                f3 = Bs[cur][(2 * t4 + 9) * 136 + col];
            }
            split2(f0, f1, bh[nt][0], bl[nt][0]);
            split2(f2, f3, bh[nt][1], bl[nt][1]);
        }

#define MMA_BF16(AF, BF)                                                     \
    asm volatile(                                                            \
        "mma.sync.aligned.m16n8k16.row.col.f32.bf16.bf16.f32 "               \
        "{%0,%1,%2,%3}, {%4,%5,%6,%7}, {%8,%9}, {%0,%1,%2,%3};"              \
        : "+f"(acc[mt][nt][0]), "+f"(acc[mt][nt][1]),                        \
          "+f"(acc[mt][nt][2]), "+f"(acc[mt][nt][3])                         \
        : "r"(AF[mt][0]), "r"(AF[mt][1]), "r"(AF[mt][2]), "r"(AF[mt][3]),    \
          "r"(BF[nt][0]), "r"(BF[nt][1]))

#pragma unroll
        for (int mt = 0; mt < 4; ++mt)
#pragma unroll
            for (int nt = 0; nt < 4; ++nt) {
                MMA_BF16(al, bh);   // lo*hi
                MMA_BF16(ah, bl);   // hi*lo
                MMA_BF16(ah, bh);   // hi*hi
            }
#undef MMA_BF16
        __syncthreads();
    }

    // Epilogue
#pragma unroll
    for (int mt = 0; mt < 4; ++mt) {
        int r0 = m0 + wm + mt * 16 + g;
#pragma unroll
        for (int nt = 0; nt < 4; ++nt) {
            int cc = n0 + wn + nt * 8 + 2 * t4;
            *(float2*)&C[(size_t)r0 * N + cc] =
                make_float2(acc[mt][nt][0], acc[mt][nt][1]);
            *(float2*)&C[(size_t)(r0 + 8) * N + cc] =
                make_float2(acc[mt][nt][2], acc[mt][nt][3]);
        }
    }
}

// ---------------------------------------------------------------------------
// 2) Gating
// ---------------------------------------------------------------------------
__global__ __launch_bounds__(256)
void gating_kernel(const float* __restrict__ X,
                   const float* __restrict__ wG,
                   const float* __restrict__ bGb)
{
    __shared__ float Gs[32];

    const int token = blockIdx.x;
    const int n = token >> 11;
    const int t = token & 2047;
    const int tid = threadIdx.x;

    {
        const int oi = tid >> 3;
        const int li = tid & 7;
        const float* xr = X + (size_t)token * DM;
        const float* wr = wG + (size_t)oi * DM;
        float acc = 0.f;
        for (int j = li; j < DM; j += 8) acc += xr[j] * wr[j];
        for (int off = 4; off; off >>= 1)
            acc += __shfl_down_sync(0xffffffffu, acc, off, 8);
        if (li == 0)
            Gs[oi] = 1.f / (1.f + __expf(-(acc + bGb[oi])));
    }
    __syncthreads();

    if (tid < E) {
        float s = 0.f;
#pragma unroll
        for (int h = 0; h < H; ++h) s += Gs[h * E + tid];
        g_A[(size_t)(n * E + tid) * T + t] = 1.f - s;
    }

    const int e = tid >> 6;
    const int d = tid & 63;
    const float* Kr = g_QKV + (size_t)token * CQKV + 512;
    const float* Vr = g_QKV + (size_t)token * CQKV + 1024;
    float ak = 0.f, av = 0.f;
#pragma unroll
    for (int h = 0; h < H; ++h) {
        float gg = Gs[h * E + e];
        ak = fmaf(gg, Kr[h * 64 + d], ak);
        av = fmaf(gg, Vr[h * 64 + d], av);
    }
    size_t o = ((size_t)(n * E + e) * T + t) * 64 + d;
    g_gK[o] = ak;
    g_gV[o] = av;
}

// ---------------------------------------------------------------------------
// 3) Scan: one thread per (n,e,s,d) runs BOTH the K and V 64-step chains.
// ---------------------------------------------------------------------------
__global__ __launch_bounds__(256)
void scan_kernel(const float* __restrict__ Aarr,
                 const float* __restrict__ gK, const float* __restrict__ gV,
                 float* __restrict__ bK, float* __restrict__ bV,
                 const float* __restrict__ iK, const float* __restrict__ iV)
{
    const int id = blockIdx.x * 256 + threadIdx.x;   // 0..16383
    const int d  = id & 63;
    const int s  = (id >> 6) & 31;
    const int e  = (id >> 11) & 3;
    const int n  = id >> 13;

    const size_t ne = (size_t)(n * E + e);

    if (s < 31) {
        bK[(ne * TBUF + s) * 64 + d] = iK[(e * L + s + 1) * 64 + d];
        bV[(ne * TBUF + s) * 64 + d] = iV[(e * L + s + 1) * 64 + d];
    }

    float SK = iK[(e * L + s) * 64 + d];
    float SV = iV[(e * L + s) * 64 + d];
    const float* Ap = Aarr + ne * T + s;
    const size_t off  = (ne * T + s) * 64 + d;
    const size_t boff = (ne * TBUF + 31 + s) * 64 + d;

#pragma unroll 4
    for (int m = 0; m < T / L; ++m) {
        float a = Ap[(size_t)32 * m];
        SK = fmaf(a, SK, gK[off + (size_t)2048 * m]);
        SV = fmaf(a, SV, gV[off + (size_t)2048 * m]);
        bK[boff + (size_t)2048 * m] = SK;
        bV[boff + (size_t)2048 * m] = SV;
    }
}

// ---------------------------------------------------------------------------
// 4) Attention: one block per token; warp w = head w; 128 state vectors.
// ---------------------------------------------------------------------------
__global__ __launch_bounds__(256)
void attn_kernel()
{
    __shared__ float kvs[128 * 65];
    __shared__ float qsh[512];
    __shared__ float sc[8 * 128];

    const int token = blockIdx.x;
    const int n = token >> 11;
    const int t = token & 2047;
    const int tid = threadIdx.x;

    for (int i = tid; i < 512; i += 256)
        qsh[i] = g_QKV[(size_t)token * CQKV + i];

    const float* bK = g_bK + (size_t)n * E * TBUF * 64;
    for (int idx = tid; idx < 128 * 64; idx += 256) {
        int row = idx >> 6, d = idx & 63;
        int e = row >> 5, j = row & 31;
        kvs[row * 65 + d] = bK[((size_t)e * TBUF + t + j) * 64 + d];
    }
    __syncthreads();

    const int w = tid >> 5;
    const int lane = tid & 31;

    float sv[4];
    float mx = -1e30f;
#pragma unroll
    for (int kk = 0; kk < 4; ++kk) {
        int j = lane + kk * 32;
        const float* qp = qsh + w * 64;
        const float* kp = kvs + j * 65;
        float acc = 0.f;
#pragma unroll
        for (int d = 0; d < 64; ++d) acc = fmaf(qp[d], kp[d], acc);
        sv[kk] = acc * 0.125f;
        mx = fmaxf(mx, sv[kk]);
    }
    for (int off = 16; off; off >>= 1)
        mx = fmaxf(mx, __shfl_xor_sync(0xffffffffu, mx, off));
    float ssum = 0.f;
#pragma unroll
    for (int kk = 0; kk < 4; ++kk) {
        sv[kk] = __expf(sv[kk] - mx);
        ssum += sv[kk];
    }
    for (int off = 16; off; off >>= 1)
        ssum += __shfl_xor_sync(0xffffffffu, ssum, off);
    float inv = 1.f / ssum;
#pragma unroll
    for (int kk = 0; kk < 4; ++kk)
        sc[w * 128 + lane + kk * 32] = sv[kk] * inv;
    __syncthreads();

    const float* bV = g_bV + (size_t)n * E * TBUF * 64;
    for (int idx = tid; idx < 128 * 64; idx += 256) {
        int row = idx >> 6, d = idx & 63;
        int e = row >> 5, j = row & 31;
        kvs[row * 65 + d] = bV[((size_t)e * TBUF + t + j) * 64 + d];
    }
    __syncthreads();

    float a0 = 0.f, a1 = 0.f;
    const float* pw = sc + w * 128;
#pragma unroll 4
    for (int j = 0; j < 128; ++j) {
        float p = pw[j];
        a0 = fmaf(p, kvs[j * 65 + lane], a0);
        a1 = fmaf(p, kvs[j * 65 + 32 + lane], a1);
    }
    g_Y[(size_t)token * 512 + w * 64 + lane]      = a0;
    g_Y[(size_t)token * 512 + w * 64 + 32 + lane] = a1;
}

// ---------------------------------------------------------------------------
// Launch
// ---------------------------------------------------------------------------
extern "C" void kernel_launch(void* const* d_in, const int* in_sizes, int n_in,
                              void* d_out, int out_size)
{
    (void)in_sizes; (void)n_in; (void)out_size;

    const float* X  = (const float*)d_in[0];
    const float* wG = (const float*)d_in[1];
    const float* bG = (const float*)d_in[2];
    const float* wK = (const float*)d_in[3];
    const float* wV = (const float*)d_in[4];
    const float* wQ = (const float*)d_in[5];
    const float* wO = (const float*)d_in[6];
    const float* iK = (const float*)d_in[7];
    const float* iV = (const float*)d_in[8];

    float *p_wQKV, *p_QKV, *p_Y, *p_A, *p_gK, *p_gV, *p_bK, *p_bV;
    cudaGetSymbolAddress((void**)&p_wQKV, g_wQKV);
    cudaGetSymbolAddress((void**)&p_QKV,  g_QKV);
    cudaGetSymbolAddress((void**)&p_Y,    g_Y);
    cudaGetSymbolAddress((void**)&p_A,    g_A);
    cudaGetSymbolAddress((void**)&p_gK,   g_gK);
    cudaGetSymbolAddress((void**)&p_gV,   g_gV);
    cudaGetSymbolAddress((void**)&p_bK,   g_bK);
    cudaGetSymbolAddress((void**)&p_bV,   g_bV);

    concat_w<<<(512 * DM + 255) / 256, 256>>>(wQ, wK, wV);
    gemm_3xbf16<0><<<dim3(NT / 128, CQKV / 128), 256>>>(X, p_wQKV, p_QKV, NT, CQKV, DM);
    gating_kernel<<<NT, 256>>>(X, wG, bG);
    scan_kernel<<<64, 256>>>(p_A, p_gK, p_gV, p_bK, p_bV, iK, iV);
    attn_kernel<<<NT, 256>>>();
    gemm_3xbf16<1><<<dim3(NT / 128, DM / 128), 256>>>(p_Y, wO, (float*)d_out, NT, DM, H * DV);
}